// round 1
// baseline (speedup 1.0000x reference)
#include <cuda_runtime.h>

// Problem constants
#define Hn 9
#define Wn 10
#define Dn 5
#define KD 3            // Dn/2 + 1
#define DIMC 1000
#define NSP (Hn*Wn*Dn)  // 450
#define CT 20           // channels per block tile (1000 / 20 = 50 tiles)
#define NTHREADS 256

// Twiddle tables: cos/sin(2*pi*m/n)
__constant__ float C5c[5]  = {1.0f, 0.30901699437494745f, -0.8090169943749473f,
                              -0.8090169943749475f, 0.30901699437494723f};
__constant__ float S5c[5]  = {0.0f, 0.9510565162951535f, 0.5877852522924732f,
                              -0.587785252292473f, -0.9510565162951536f};
__constant__ float C9c[9]  = {1.0f, 0.766044443118978f, 0.17364817766693041f,
                              -0.4999999999999998f, -0.9396926207859083f,
                              -0.9396926207859084f, -0.5000000000000004f,
                              0.17364817766693017f, 0.7660444431189778f};
__constant__ float S9c[9]  = {0.0f, 0.6427876096865393f, 0.984807753012208f,
                              0.8660254037844387f, 0.34202014332566893f,
                              -0.34202014332566866f, -0.8660254037844385f,
                              -0.9848077530122081f, -0.6427876096865396f};
__constant__ float C10c[10] = {1.0f, 0.8090169943749475f, 0.30901699437494745f,
                               -0.30901699437494734f, -0.8090169943749473f, -1.0f,
                               -0.8090169943749475f, -0.30901699437494756f,
                               0.30901699437494723f, 0.8090169943749475f};
__constant__ float S10c[10] = {0.0f, 0.5877852522924731f, 0.9510565162951535f,
                               0.9510565162951536f, 0.5877852522924732f, 0.0f,
                               -0.587785252292473f, -0.9510565162951535f,
                               -0.9510565162951536f, -0.5877852522924734f};

// Shared half-spectrum layout: [hw (0..89)][k (0..2)][c (0..CT-1)], split re/im.
__global__ void __launch_bounds__(NTHREADS)
gf_kernel(const float* __restrict__ x, const float* __restrict__ cw,
          float* __restrict__ out)
{
    __shared__ float zr[Hn*Wn*KD*CT];   // 21.6 KB
    __shared__ float zi[Hn*Wn*KD*CT];   // 21.6 KB

    const int b   = blockIdx.x;
    const int c0  = blockIdx.y * CT;
    const int tid = threadIdx.x;
    const long xbase = (long)b * NSP * DIMC + c0;

    // ---- Phase 1: load x, rfft along d (5 real -> 3 complex), e^{-i}
    for (int it = tid; it < Hn*Wn*CT; it += NTHREADS) {
        int c  = it % CT;
        int hw = it / CT;
        const float* px = x + xbase + (long)hw * (Dn*DIMC) + c;
        float v0 = px[0],        v1 = px[DIMC],   v2 = px[2*DIMC];
        float v3 = px[3*DIMC],   v4 = px[4*DIMC];
        int sb = (hw*KD)*CT + c;
        zr[sb]      = v0 + v1 + v2 + v3 + v4;
        zi[sb]      = 0.0f;
        // k=1: indices d%5 = 1,2,3,4
        zr[sb+CT]   = v0 + v1*C5c[1] + v2*C5c[2] + v3*C5c[3] + v4*C5c[4];
        zi[sb+CT]   = -(v1*S5c[1] + v2*S5c[2] + v3*S5c[3] + v4*S5c[4]);
        // k=2: indices (2d)%5 = 2,4,1,3
        zr[sb+2*CT] = v0 + v1*C5c[2] + v2*C5c[4] + v3*C5c[1] + v4*C5c[3];
        zi[sb+2*CT] = -(v1*S5c[2] + v2*S5c[4] + v3*S5c[1] + v4*S5c[3]);
    }
    __syncthreads();

    // ---- Phase 2: forward FFT along w (10-pt dense), e^{-i}
    for (int it = tid; it < Hn*KD*CT; it += NTHREADS) {
        int c  = it % CT;
        int hk = it / CT;
        int h = hk / KD, k = hk % KD;
        int base = (h*Wn*KD + k)*CT + c;
        float xr[Wn], xm[Wn];
        #pragma unroll
        for (int w = 0; w < Wn; w++) {
            xr[w] = zr[base + w*KD*CT];
            xm[w] = zi[base + w*KD*CT];
        }
        #pragma unroll
        for (int j = 0; j < Wn; j++) {
            float ar = xr[0], ai = xm[0];
            #pragma unroll
            for (int w = 1; w < Wn; w++) {
                const int m = (j*w) % Wn;
                ar += xr[w]*C10c[m] + xm[w]*S10c[m];
                ai += xm[w]*C10c[m] - xr[w]*S10c[m];
            }
            zr[base + j*KD*CT] = ar;
            zi[base + j*KD*CT] = ai;
        }
    }
    __syncthreads();

    // ---- Phase 3: forward FFT along h (9-pt dense), e^{-i}
    for (int it = tid; it < Wn*KD*CT; it += NTHREADS) {
        int c  = it % CT;
        int wk = it / CT;
        int w = wk / KD, k = wk % KD;
        int base = (w*KD + k)*CT + c;
        float xr[Hn], xm[Hn];
        #pragma unroll
        for (int h = 0; h < Hn; h++) {
            xr[h] = zr[base + h*Wn*KD*CT];
            xm[h] = zi[base + h*Wn*KD*CT];
        }
        #pragma unroll
        for (int j = 0; j < Hn; j++) {
            float ar = xr[0], ai = xm[0];
            #pragma unroll
            for (int h = 1; h < Hn; h++) {
                const int m = (j*h) % Hn;
                ar += xr[h]*C9c[m] + xm[h]*S9c[m];
                ai += xm[h]*C9c[m] - xr[h]*S9c[m];
            }
            zr[base + j*Wn*KD*CT] = ar;
            zi[base + j*Wn*KD*CT] = ai;
        }
    }
    __syncthreads();

    // ---- Phase 4: complex weight multiply, folded ortho scale 1/450
    {
        const float sc = 1.0f / 450.0f;
        for (int it = tid; it < Hn*Wn*KD*CT; it += NTHREADS) {
            int c = it % CT;
            int f = it / CT;                 // (h*10+w)*3 + k, matches weight layout
            long wbase = ((long)f*DIMC + c0 + c) * 2;
            float wr = cw[wbase], wi = cw[wbase + 1];
            int sb = f*CT + c;
            float a = zr[sb], bb = zi[sb];
            zr[sb] = (a*wr - bb*wi) * sc;
            zi[sb] = (a*wi + bb*wr) * sc;
        }
    }
    __syncthreads();

    // ---- Phase 5: inverse FFT along h (9-pt dense), e^{+i}, no 1/N
    for (int it = tid; it < Wn*KD*CT; it += NTHREADS) {
        int c  = it % CT;
        int wk = it / CT;
        int w = wk / KD, k = wk % KD;
        int base = (w*KD + k)*CT + c;
        float xr[Hn], xm[Hn];
        #pragma unroll
        for (int h = 0; h < Hn; h++) {
            xr[h] = zr[base + h*Wn*KD*CT];
            xm[h] = zi[base + h*Wn*KD*CT];
        }
        #pragma unroll
        for (int j = 0; j < Hn; j++) {
            float ar = xr[0], ai = xm[0];
            #pragma unroll
            for (int h = 1; h < Hn; h++) {
                const int m = (j*h) % Hn;
                ar += xr[h]*C9c[m] - xm[h]*S9c[m];
                ai += xr[h]*S9c[m] + xm[h]*C9c[m];
            }
            zr[base + j*Wn*KD*CT] = ar;
            zi[base + j*Wn*KD*CT] = ai;
        }
    }
    __syncthreads();

    // ---- Phase 6: inverse FFT along w (10-pt dense), e^{+i}, no 1/N
    for (int it = tid; it < Hn*KD*CT; it += NTHREADS) {
        int c  = it % CT;
        int hk = it / CT;
        int h = hk / KD, k = hk % KD;
        int base = (h*Wn*KD + k)*CT + c;
        float xr[Wn], xm[Wn];
        #pragma unroll
        for (int w = 0; w < Wn; w++) {
            xr[w] = zr[base + w*KD*CT];
            xm[w] = zi[base + w*KD*CT];
        }
        #pragma unroll
        for (int j = 0; j < Wn; j++) {
            float ar = xr[0], ai = xm[0];
            #pragma unroll
            for (int w = 1; w < Wn; w++) {
                const int m = (j*w) % Wn;
                ar += xr[w]*C10c[m] - xm[w]*S10c[m];
                ai += xr[w]*S10c[m] + xm[w]*C10c[m];
            }
            zr[base + j*KD*CT] = ar;
            zi[base + j*KD*CT] = ai;
        }
    }
    __syncthreads();

    // ---- Phase 7: irfft along d (3 complex -> 5 real) + store
    // y[d] = Re(Z0) + 2*Re(Z1 e^{+2pi i d/5}) + 2*Re(Z2 e^{+2pi i 2d/5})
    for (int it = tid; it < Hn*Wn*CT; it += NTHREADS) {
        int c  = it % CT;
        int hw = it / CT;
        int sb = (hw*KD)*CT + c;
        float a0 = zr[sb];
        float r1 = zr[sb+CT],   i1 = zi[sb+CT];
        float r2 = zr[sb+2*CT], i2 = zi[sb+2*CT];
        float* po = out + xbase + (long)hw * (Dn*DIMC) + c;
        #pragma unroll
        for (int d = 0; d < Dn; d++) {
            const int m1 = d;           // (1*d)%5
            const int m2 = (2*d) % Dn;
            float y = a0 + 2.0f*(r1*C5c[m1] - i1*S5c[m1])
                         + 2.0f*(r2*C5c[m2] - i2*S5c[m2]);
            po[d*DIMC] = y;
        }
    }
}

extern "C" void kernel_launch(void* const* d_in, const int* in_sizes, int n_in,
                              void* d_out, int out_size) {
    const float* x  = (const float*)d_in[0];   // (B, 450, 1000) f32
    const float* cw = (const float*)d_in[1];   // (9, 10, 3, 1000, 2) f32
    float* out = (float*)d_out;                // (B, 450, 1000) f32
    const int B = in_sizes[0] / (NSP * DIMC);
    dim3 grid(B, DIMC / CT);
    gf_kernel<<<grid, NTHREADS>>>(x, cw, out);
}

// round 2
// speedup vs baseline: 2.2484x; 2.2484x over previous
#include <cuda_runtime.h>

#define Hn 9
#define Wn 10
#define Dn 5
#define KD 3            // Dn/2 + 1
#define DIMC 1000
#define NSP (Hn*Wn*Dn)  // 450
#define CT 20           // channels per block tile
#define NTHREADS 256
#define SC (1.0f/450.0f)

// ---- compile-time twiddle literals (become FFMA immediates) ----
#define C51  0.30901699437494745f   // cos(2pi/5)
#define C52 (-0.8090169943749475f)  // cos(4pi/5)
#define S51  0.9510565162951535f    // sin(2pi/5)
#define S52  0.5877852522924731f    // sin(4pi/5)
#define S3   0.8660254037844386f    // sqrt(3)/2
#define C91  0.766044443118978f     // cos(2pi/9)
#define S91  0.6427876096865393f    // sin(2pi/9)
#define C92  0.17364817766693041f   // cos(4pi/9)
#define S92  0.984807753012208f     // sin(4pi/9)
#define C94 (-0.9396926207859084f)  // cos(8pi/9)
#define S94  0.3420201433256687f    // sin(8pi/9)
#define C101 0.8090169943749475f    // cos(pi/5)
#define S101 0.5877852522924731f    // sin(pi/5)
#define C102 0.30901699437494745f   // cos(2pi/5)
#define S102 0.9510565162951535f    // sin(2pi/5)

__device__ __forceinline__ float2 cadd(float2 a, float2 b){ return make_float2(a.x+b.x, a.y+b.y); }
__device__ __forceinline__ float2 csub(float2 a, float2 b){ return make_float2(a.x-b.x, a.y-b.y); }
// multiply by (c + i s)
__device__ __forceinline__ float2 cmul(float2 a, float c, float s){
    return make_float2(a.x*c - a.y*s, a.y*c + a.x*s);
}

// 3-pt DFT. SGN=+1: kernel e^{-i2pi/3}; SGN=-1: e^{+i2pi/3}
template<int SGN>
__device__ __forceinline__ void dft3(float2 a0, float2 a1, float2 a2,
                                     float2& X0, float2& X1, float2& X2){
    float2 t = cadd(a1,a2), d = csub(a1,a2);
    X0 = cadd(a0,t);
    float mr = fmaf(-0.5f, t.x, a0.x);
    float mi = fmaf(-0.5f, t.y, a0.y);
    const float s = (SGN > 0) ? S3 : -S3;
    X1 = make_float2(fmaf( s, d.y, mr), fmaf(-s, d.x, mi));
    X2 = make_float2(fmaf(-s, d.y, mr), fmaf( s, d.x, mi));
}

// 5-pt DFT. SGN=+1 forward (e^{-i}); SGN=-1 inverse
template<int SGN>
__device__ __forceinline__ void dft5(float2 a0, float2 a1, float2 a2, float2 a3, float2 a4,
                                     float2& X0, float2& X1, float2& X2, float2& X3, float2& X4){
    float2 t1 = cadd(a1,a4), t2 = cadd(a2,a3), t3 = csub(a1,a4), t4 = csub(a2,a3);
    X0 = make_float2(a0.x + t1.x + t2.x, a0.y + t1.y + t2.y);
    float u1r = a0.x + C51*t1.x + C52*t2.x;
    float u1i = a0.y + C51*t1.y + C52*t2.y;
    float v1r = S51*t3.x + S52*t4.x;
    float v1i = S51*t3.y + S52*t4.y;
    float u2r = a0.x + C52*t1.x + C51*t2.x;
    float u2i = a0.y + C52*t1.y + C51*t2.y;
    float v2r = S52*t3.x - S51*t4.x;
    float v2i = S52*t3.y - S51*t4.y;
    if (SGN > 0){
        X1 = make_float2(u1r + v1i, u1i - v1r);
        X4 = make_float2(u1r - v1i, u1i + v1r);
        X2 = make_float2(u2r + v2i, u2i - v2r);
        X3 = make_float2(u2r - v2i, u2i + v2r);
    } else {
        X1 = make_float2(u1r - v1i, u1i + v1r);
        X4 = make_float2(u1r + v1i, u1i - v1r);
        X2 = make_float2(u2r - v2i, u2i + v2r);
        X3 = make_float2(u2r + v2i, u2i - v2r);
    }
}

// 10-pt FFT, radix 2x5 DIT, in place on shared (stride in float2 elems)
template<int SGN>
__device__ __forceinline__ void fft10(float2* z, int base, int stride){
    float2 x0=z[base+0*stride], x1=z[base+1*stride], x2=z[base+2*stride],
           x3=z[base+3*stride], x4=z[base+4*stride], x5=z[base+5*stride],
           x6=z[base+6*stride], x7=z[base+7*stride], x8=z[base+8*stride],
           x9=z[base+9*stride];
    float2 E0,E1,E2,E3,E4, O0,O1,O2,O3,O4;
    dft5<SGN>(x0,x2,x4,x6,x8, E0,E1,E2,E3,E4);
    dft5<SGN>(x1,x3,x5,x7,x9, O0,O1,O2,O3,O4);
    const float sg = (SGN > 0) ? -1.0f : 1.0f;   // sign of sin in omega10^j
    float2 T1 = cmul(O1,  C101, sg*S101);
    float2 T2 = cmul(O2,  C102, sg*S102);
    float2 T3 = cmul(O3, -C102, sg*S102);
    float2 T4 = cmul(O4, -C101, sg*S101);
    z[base+0*stride] = cadd(E0,O0);  z[base+5*stride] = csub(E0,O0);
    z[base+1*stride] = cadd(E1,T1);  z[base+6*stride] = csub(E1,T1);
    z[base+2*stride] = cadd(E2,T2);  z[base+7*stride] = csub(E2,T2);
    z[base+3*stride] = cadd(E3,T3);  z[base+8*stride] = csub(E3,T3);
    z[base+4*stride] = cadd(E4,T4);  z[base+9*stride] = csub(E4,T4);
}

// Shared layout: z[((h*Wn + w)*KD + k)*CT + c] as float2 (re, im)
__global__ void __launch_bounds__(NTHREADS, 3)
gf_kernel(const float* __restrict__ x, const float2* __restrict__ cw2,
          float* __restrict__ out)
{
    __shared__ float2 z[Hn*Wn*KD*CT];   // 43.2 KB

    const int b   = blockIdx.x;
    const int c0  = blockIdx.y * CT;
    const int tid = threadIdx.x;
    const long xbase = (long)b * NSP * DIMC + c0;

    // ---- Phase 1: load x, rfft along d (5 real -> 3 complex)
    for (int it = tid; it < Hn*Wn*CT; it += NTHREADS) {
        int c  = it % CT;
        int hw = it / CT;
        const float* px = x + xbase + (long)hw * (Dn*DIMC) + c;
        float v0 = px[0],      v1 = px[DIMC],   v2 = px[2*DIMC];
        float v3 = px[3*DIMC], v4 = px[4*DIMC];
        float t1 = v1+v4, t2 = v2+v3, t3 = v1-v4, t4 = v2-v3;
        int sb = (hw*KD)*CT + c;
        z[sb]      = make_float2(v0 + t1 + t2, 0.0f);
        z[sb+CT]   = make_float2(v0 + C51*t1 + C52*t2, -(S51*t3 + S52*t4));
        z[sb+2*CT] = make_float2(v0 + C52*t1 + C51*t2, -(S52*t3 - S51*t4));
    }
    __syncthreads();

    // ---- Phase 2: forward FFT along w (radix 2x5)
    for (int it = tid; it < Hn*KD*CT; it += NTHREADS) {
        int c  = it % CT;
        int hk = it / CT;
        int h = hk / KD, k = hk % KD;
        fft10<+1>(z, (h*Wn*KD + k)*CT + c, KD*CT);
    }
    __syncthreads();

    // ---- Phase 3: fwd 9-pt (3x3) -> weight -> inv 9-pt, fused in registers
    {
        const int HS = Wn*KD*CT;   // h stride in float2 elems
        for (int it = tid; it < Wn*KD*CT; it += NTHREADS) {
            int c  = it % CT;
            int wk = it / CT;
            int w = wk / KD, k = wk % KD;
            int base = (w*KD + k)*CT + c;
            float2 a0=z[base+0*HS], a1=z[base+1*HS], a2=z[base+2*HS],
                   a3=z[base+3*HS], a4=z[base+4*HS], a5=z[base+5*HS],
                   a6=z[base+6*HS], a7=z[base+7*HS], a8=z[base+8*HS];
            // stage 1: DFT3 over n1 within column n2 (n = 3*n1 + n2)
            float2 A00,A10,A20, A01,A11,A21, A02,A12,A22;
            dft3<+1>(a0,a3,a6, A00,A10,A20);
            dft3<+1>(a1,a4,a7, A01,A11,A21);
            dft3<+1>(a2,a5,a8, A02,A12,A22);
            // twiddle B[j1][n2] = A * omega9^{j1*n2} (e^{-i})
            A11 = cmul(A11, C91, -S91);
            A12 = cmul(A12, C92, -S92);
            A21 = cmul(A21, C92, -S92);
            A22 = cmul(A22, C94, -S94);
            // stage 2: DFT3 over n2 -> X[j1 + 3*j2]
            float2 X0,X3,X6, X1,X4,X7, X2,X5,X8;
            dft3<+1>(A00,A01,A02, X0,X3,X6);
            dft3<+1>(A10,A11,A12, X1,X4,X7);
            dft3<+1>(A20,A21,A22, X2,X5,X8);
            // weight multiply (freq bin j along h)
            const float2* cwp = cw2 + (long)((w*KD) + k)*DIMC + c0 + c;
            const int WS = Wn*KD*DIMC;  // h stride in weight
            {
                float2 g;
                g = cwp[0*WS]; X0 = make_float2(X0.x*g.x - X0.y*g.y, X0.x*g.y + X0.y*g.x);
                g = cwp[1*WS]; X1 = make_float2(X1.x*g.x - X1.y*g.y, X1.x*g.y + X1.y*g.x);
                g = cwp[2*WS]; X2 = make_float2(X2.x*g.x - X2.y*g.y, X2.x*g.y + X2.y*g.x);
                g = cwp[3*WS]; X3 = make_float2(X3.x*g.x - X3.y*g.y, X3.x*g.y + X3.y*g.x);
                g = cwp[4*WS]; X4 = make_float2(X4.x*g.x - X4.y*g.y, X4.x*g.y + X4.y*g.x);
                g = cwp[5*WS]; X5 = make_float2(X5.x*g.x - X5.y*g.y, X5.x*g.y + X5.y*g.x);
                g = cwp[6*WS]; X6 = make_float2(X6.x*g.x - X6.y*g.y, X6.x*g.y + X6.y*g.x);
                g = cwp[7*WS]; X7 = make_float2(X7.x*g.x - X7.y*g.y, X7.x*g.y + X7.y*g.x);
                g = cwp[8*WS]; X8 = make_float2(X8.x*g.x - X8.y*g.y, X8.x*g.y + X8.y*g.x);
            }
            // inverse 9-pt: groups over b: (X0,X3,X6)(X1,X4,X7)(X2,X5,X8)
            float2 P00,P10,P20, P01,P11,P21, P02,P12,P22;
            dft3<-1>(X0,X3,X6, P00,P10,P20);
            dft3<-1>(X1,X4,X7, P01,P11,P21);
            dft3<-1>(X2,X5,X8, P02,P12,P22);
            P11 = cmul(P11, C91, S91);
            P12 = cmul(P12, C92, S92);
            P21 = cmul(P21, C92, S92);
            P22 = cmul(P22, C94, S94);
            float2 y0,y3,y6, y1,y4,y7, y2,y5,y8;
            dft3<-1>(P00,P01,P02, y0,y3,y6);
            dft3<-1>(P10,P11,P12, y1,y4,y7);
            dft3<-1>(P20,P21,P22, y2,y5,y8);
            z[base+0*HS]=y0; z[base+1*HS]=y1; z[base+2*HS]=y2;
            z[base+3*HS]=y3; z[base+4*HS]=y4; z[base+5*HS]=y5;
            z[base+6*HS]=y6; z[base+7*HS]=y7; z[base+8*HS]=y8;
        }
    }
    __syncthreads();

    // ---- Phase 4: inverse FFT along w (radix 2x5)
    for (int it = tid; it < Hn*KD*CT; it += NTHREADS) {
        int c  = it % CT;
        int hk = it / CT;
        int h = hk / KD, k = hk % KD;
        fft10<-1>(z, (h*Wn*KD + k)*CT + c, KD*CT);
    }
    __syncthreads();

    // ---- Phase 5: irfft along d (3 complex -> 5 real) + scale + store
    for (int it = tid; it < Hn*Wn*CT; it += NTHREADS) {
        int c  = it % CT;
        int hw = it / CT;
        int sb = (hw*KD)*CT + c;
        float  a0 = z[sb].x * SC;
        float2 z1 = z[sb+CT], z2 = z[sb+2*CT];
        float r1 = z1.x*SC, i1 = z1.y*SC, r2 = z2.x*SC, i2 = z2.y*SC;
        float pA = a0 + 2.0f*(C51*r1 + C52*r2);
        float qA = 2.0f*(S51*i1 + S52*i2);
        float pB = a0 + 2.0f*(C52*r1 + C51*r2);
        float qB = 2.0f*(S52*i1 - S51*i2);
        float* po = out + xbase + (long)hw * (Dn*DIMC) + c;
        po[0]      = a0 + 2.0f*(r1 + r2);
        po[DIMC]   = pA - qA;
        po[2*DIMC] = pB - qB;
        po[3*DIMC] = pB + qB;
        po[4*DIMC] = pA + qA;
    }
}

extern "C" void kernel_launch(void* const* d_in, const int* in_sizes, int n_in,
                              void* d_out, int out_size) {
    const float*  x   = (const float*)d_in[0];    // (B, 450, 1000) f32
    const float2* cw2 = (const float2*)d_in[1];   // (9, 10, 3, 1000, 2) f32 -> float2
    float* out = (float*)d_out;                   // (B, 450, 1000) f32
    const int B = in_sizes[0] / (NSP * DIMC);
    dim3 grid(B, DIMC / CT);
    gf_kernel<<<grid, NTHREADS>>>(x, cw2, out);
}